// round 1
// baseline (speedup 1.0000x reference)
#include <cuda_runtime.h>
#include <math.h>

// Problem constants
#define NCB    8
#define KCODES 1024
#define CD     64
#define BB     8
#define TSEQ   2048
#define DD     512
#define NTOK   (BB * TSEQ)     // 16384

// Tiling
#define TILE_T   64
#define TILE_K   128
#define NTHREADS 128
#define RES_P    68            // res smem pitch (floats), [d][t]
#define CB_P     132           // cb  smem pitch (floats), [d][k]

// smem layout (floats): cb | res | rn | cbn | bestv | besti(int)
#define OFF_CB    0
#define OFF_RES   (OFF_CB + 64 * CB_P)          // 8448
#define OFF_RN    (OFF_RES + 64 * RES_P)        // +4352
#define OFF_CBN   (OFF_RN + TILE_T)
#define OFF_BESTV (OFF_CBN + TILE_K)
#define OFF_BESTI (OFF_BESTV + TILE_T)
#define SMEM_FLOATS (OFF_BESTI + TILE_T)
#define SMEM_BYTES  (SMEM_FLOATS * 4)

typedef unsigned long long ull;

__device__ __forceinline__ ull dup_f32x2(float x) {
    ull r;
    asm("mov.b64 %0, {%1, %1};" : "=l"(r) : "f"(x));
    return r;
}
__device__ __forceinline__ void fma_f32x2(ull &acc, ull a, ull b) {
    asm("fma.rn.f32x2 %0, %1, %2, %0;" : "+l"(acc) : "l"(a), "l"(b));
}
__device__ __forceinline__ float2 unpack_f32x2(ull p) {
    float2 f;
    asm("mov.b64 {%0, %1}, %2;" : "=f"(f.x), "=f"(f.y) : "l"(p));
    return f;
}

__global__ void __launch_bounds__(NTHREADS, 2)
rvq_kernel(const float* __restrict__ z,
           const float* __restrict__ cbooks,
           float* __restrict__ outZq,
           float* __restrict__ outIdx,
           float* __restrict__ outLogits)
{
    extern __shared__ float smem[];
    float* cb_s    = smem + OFF_CB;
    float* res_s   = smem + OFF_RES;
    float* rn_s    = smem + OFF_RN;
    float* cbn_s   = smem + OFF_CBN;
    float* bestv_s = smem + OFF_BESTV;
    int*   besti_s = (int*)(smem + OFF_BESTI);

    const int tid     = threadIdx.x;
    const int tokBase = blockIdx.x * TILE_T;

    // GEMM thread mapping: 8 token-groups x 16 code-groups
    const int ty = tid >> 4;        // 0..7
    const int tx = tid & 15;        // 0..15
    const int t0 = ty * 8;
    const int c0 = tx * 4;

    // ---- init: res = z chunk 0 (transposed into smem), rn = ||res||^2 ----
    {
        const int t = tid >> 1, h = tid & 1;
        const int tok = tokBase + t;
        const float4* z4p = (const float4*)(z + (size_t)tok * DD) + h * 8;
        float sq = 0.f;
        #pragma unroll
        for (int j = 0; j < 8; j++) {
            float4 zv = z4p[j];
            int d = h * 32 + j * 4;
            res_s[(d + 0) * RES_P + t] = zv.x;
            res_s[(d + 1) * RES_P + t] = zv.y;
            res_s[(d + 2) * RES_P + t] = zv.z;
            res_s[(d + 3) * RES_P + t] = zv.w;
            sq += zv.x * zv.x + zv.y * zv.y + zv.z * zv.z + zv.w * zv.w;
        }
        float o = __shfl_xor_sync(0xffffffffu, sq, 1);
        if (h == 0) rn_s[t] = sq + o;
    }

    for (int i = 0; i < NCB; i++) {
        if (tid < TILE_T) { bestv_s[tid] = 3.4e38f; besti_s[tid] = 0; }
        __syncthreads();   // res_s, rn_s, best init ready

        for (int kb = 0; kb < KCODES / TILE_K; kb++) {
            // ---- load cb block, transposed (register transpose, STS.128) ----
            const float4* cbG =
                (const float4*)(cbooks + ((size_t)i * KCODES + (size_t)kb * TILE_K) * CD);
            #pragma unroll
            for (int r = 0; r < 4; r++) {
                int u  = tid + r * NTHREADS;          // 0..511
                int k0 = (u & 31) * 4;                // code base
                int dg = u >> 5;                      // dim group 0..15
                float4 v0 = cbG[(k0 + 0) * 16 + dg];
                float4 v1 = cbG[(k0 + 1) * 16 + dg];
                float4 v2 = cbG[(k0 + 2) * 16 + dg];
                float4 v3 = cbG[(k0 + 3) * 16 + dg];
                int d0 = dg * 4;
                *(float4*)(cb_s + (d0 + 0) * CB_P + k0) = make_float4(v0.x, v1.x, v2.x, v3.x);
                *(float4*)(cb_s + (d0 + 1) * CB_P + k0) = make_float4(v0.y, v1.y, v2.y, v3.y);
                *(float4*)(cb_s + (d0 + 2) * CB_P + k0) = make_float4(v0.z, v1.z, v2.z, v3.z);
                *(float4*)(cb_s + (d0 + 3) * CB_P + k0) = make_float4(v0.w, v1.w, v2.w, v3.w);
            }
            __syncthreads();

            // ---- code norms (one code per thread) ----
            {
                float s = 0.f;
                #pragma unroll 16
                for (int d = 0; d < CD; d++) {
                    float v = cb_s[d * CB_P + tid];
                    s += v * v;
                }
                cbn_s[tid] = s;
            }

            // ---- GEMM: 8 tokens x 8 codes per thread, f32x2 packed FMA ----
            ull acc[8][4];
            #pragma unroll
            for (int a = 0; a < 8; a++)
                #pragma unroll
                for (int b = 0; b < 4; b++) acc[a][b] = 0ull;

            #pragma unroll 16
            for (int d = 0; d < CD; d++) {
                const float* rp = res_s + d * RES_P + t0;
                float4 ra = *(const float4*)rp;
                float4 rb = *(const float4*)(rp + 4);
                const float* cp = cb_s + d * CB_P + c0;
                ulonglong2 cA = *(const ulonglong2*)cp;          // codes c0,c0+1 | c0+2,c0+3
                ulonglong2 cB = *(const ulonglong2*)(cp + 64);   // codes +64
                float rv[8] = {ra.x, ra.y, ra.z, ra.w, rb.x, rb.y, rb.z, rb.w};
                #pragma unroll
                for (int tt = 0; tt < 8; tt++) {
                    ull r = dup_f32x2(rv[tt]);
                    fma_f32x2(acc[tt][0], r, cA.x);
                    fma_f32x2(acc[tt][1], r, cA.y);
                    fma_f32x2(acc[tt][2], r, cB.x);
                    fma_f32x2(acc[tt][3], r, cB.y);
                }
            }
            __syncthreads();   // cbn_s visible; GEMM smem reads done

            // ---- epilogue: logits store + per-token argmin ----
            {
                const float cn0 = cbn_s[c0 + 0], cn1 = cbn_s[c0 + 1];
                const float cn2 = cbn_s[c0 + 2], cn3 = cbn_s[c0 + 3];
                const float cn4 = cbn_s[c0 + 64], cn5 = cbn_s[c0 + 65];
                const float cn6 = cbn_s[c0 + 66], cn7 = cbn_s[c0 + 67];
                const int cg = kb * TILE_K + c0;

                #pragma unroll
                for (int tt = 0; tt < 8; tt++) {
                    const int t   = t0 + tt;
                    const int tok = tokBase + t;
                    const int b   = tok >> 11;
                    const int tl  = tok & (TSEQ - 1);
                    const float rn = rn_s[t];

                    float2 p0 = unpack_f32x2(acc[tt][0]);
                    float2 p1 = unpack_f32x2(acc[tt][1]);
                    float2 p2 = unpack_f32x2(acc[tt][2]);
                    float2 p3 = unpack_f32x2(acc[tt][3]);

                    float4 oA = make_float4(2.f * p0.x - rn - cn0, 2.f * p0.y - rn - cn1,
                                            2.f * p1.x - rn - cn2, 2.f * p1.y - rn - cn3);
                    float4 oB = make_float4(2.f * p2.x - rn - cn4, 2.f * p2.y - rn - cn5,
                                            2.f * p3.x - rn - cn6, 2.f * p3.y - rn - cn7);

                    size_t base = (((size_t)(b * NCB + i)) * TSEQ + tl) * KCODES;
                    *(float4*)(outLogits + base + cg)      = oA;
                    *(float4*)(outLogits + base + cg + 64) = oB;

                    // argmin key = cbn - 2*dot = -logit - rn  (rn cancels per token)
                    float mv = -oA.x - rn; int mi = cg;
                    float v;
                    v = -oA.y - rn; if (v < mv) { mv = v; mi = cg + 1; }
                    v = -oA.z - rn; if (v < mv) { mv = v; mi = cg + 2; }
                    v = -oA.w - rn; if (v < mv) { mv = v; mi = cg + 3; }
                    v = -oB.x - rn; if (v < mv) { mv = v; mi = cg + 64; }
                    v = -oB.y - rn; if (v < mv) { mv = v; mi = cg + 65; }
                    v = -oB.z - rn; if (v < mv) { mv = v; mi = cg + 66; }
                    v = -oB.w - rn; if (v < mv) { mv = v; mi = cg + 67; }

                    #pragma unroll
                    for (int off = 8; off > 0; off >>= 1) {
                        float ov = __shfl_xor_sync(0xffffffffu, mv, off);
                        int   oi = __shfl_xor_sync(0xffffffffu, mi, off);
                        if (ov < mv || (ov == mv && oi < mi)) { mv = ov; mi = oi; }
                    }
                    if (tx == 0) {
                        if (mv < bestv_s[t]) { bestv_s[t] = mv; besti_s[t] = mi; }
                    }
                }
            }
            __syncthreads();   // best final for this kb; cb_s/cbn_s reusable
        }

        // ---- finish stage: indices, z_q, residual update, new rn ----
        if (tid < TILE_T) {
            const int t = tid;
            const int tok = tokBase + t;
            const int b = tok >> 11, tl = tok & (TSEQ - 1);
            outIdx[((size_t)b * NCB + i) * TSEQ + tl] = (float)besti_s[t];
        }
        {
            const int t = tid >> 1, h = tid & 1;
            const int tok = tokBase + t;
            const int idx = besti_s[t];
            const float4* q4p =
                (const float4*)(cbooks + ((size_t)i * KCODES + idx) * CD) + h * 8;
            float4* zq4p = (float4*)(outZq + (size_t)tok * DD + i * CD) + h * 8;
            float sq = 0.f;
            if (i < NCB - 1) {
                const float4* z4p =
                    (const float4*)(z + (size_t)tok * DD + (i + 1) * CD) + h * 8;
                #pragma unroll
                for (int j = 0; j < 8; j++) {
                    float4 q = q4p[j];
                    zq4p[j] = q;
                    float4 zv = z4p[j];
                    int d = h * 32 + j * 4;
                    float r0 = zv.x + res_s[(d + 0) * RES_P + t] - q.x;
                    float r1 = zv.y + res_s[(d + 1) * RES_P + t] - q.y;
                    float r2 = zv.z + res_s[(d + 2) * RES_P + t] - q.z;
                    float r3 = zv.w + res_s[(d + 3) * RES_P + t] - q.w;
                    res_s[(d + 0) * RES_P + t] = r0;
                    res_s[(d + 1) * RES_P + t] = r1;
                    res_s[(d + 2) * RES_P + t] = r2;
                    res_s[(d + 3) * RES_P + t] = r3;
                    sq += r0 * r0 + r1 * r1 + r2 * r2 + r3 * r3;
                }
                float o = __shfl_xor_sync(0xffffffffu, sq, 1);
                if (h == 0) rn_s[t] = sq + o;
            } else {
                #pragma unroll
                for (int j = 0; j < 8; j++) zq4p[j] = q4p[j];
            }
        }
        // loop-top __syncthreads() guards res_s/rn_s for next stage
    }
}

extern "C" void kernel_launch(void* const* d_in, const int* in_sizes, int n_in,
                              void* d_out, int out_size) {
    const float* z      = (const float*)d_in[0];   // (8, 2048, 512) f32
    const float* cbooks = (const float*)d_in[1];   // (8, 1024, 64)  f32

    float* outZq     = (float*)d_out;                               // 8388608
    float* outIdx    = outZq + (size_t)NTOK * DD;                   // 131072
    float* outLogits = outIdx + (size_t)BB * NCB * TSEQ;            // 134217728

    cudaFuncSetAttribute(rvq_kernel, cudaFuncAttributeMaxDynamicSharedMemorySize,
                         SMEM_BYTES);
    rvq_kernel<<<NTOK / TILE_T, NTHREADS, SMEM_BYTES>>>(z, cbooks, outZq, outIdx,
                                                        outLogits);
}

// round 2
// speedup vs baseline: 1.0005x; 1.0005x over previous
#include <cuda_runtime.h>
#include <math.h>

// Problem constants
#define NCB    8
#define KCODES 1024
#define CD     64
#define BB     8
#define TSEQ   2048
#define DD     512
#define NTOK   (BB * TSEQ)     // 16384

// Tiling
#define TILE_T   64
#define TILE_K   128
#define NTHREADS 128
#define RES_P    68            // res smem pitch (floats), [d][t]
#define CB_P     132           // cb  smem pitch (floats), [d][k]

// smem layout (floats): cb | res | rn | cbn | bestv | besti(int)
#define OFF_CB    0
#define OFF_RES   (OFF_CB + 64 * CB_P)          // 8448
#define OFF_RN    (OFF_RES + 64 * RES_P)        // +4352
#define OFF_CBN   (OFF_RN + TILE_T)
#define OFF_BESTV (OFF_CBN + TILE_K)
#define OFF_BESTI (OFF_BESTV + TILE_T)
#define SMEM_FLOATS (OFF_BESTI + TILE_T)
#define SMEM_BYTES  (SMEM_FLOATS * 4)

typedef unsigned long long ull;

__device__ __forceinline__ ull dup_f32x2(float x) {
    ull r;
    asm("mov.b64 %0, {%1, %1};" : "=l"(r) : "f"(x));
    return r;
}
__device__ __forceinline__ void fma_f32x2(ull &acc, ull a, ull b) {
    asm("fma.rn.f32x2 %0, %1, %2, %0;" : "+l"(acc) : "l"(a), "l"(b));
}
__device__ __forceinline__ float2 unpack_f32x2(ull p) {
    float2 f;
    asm("mov.b64 {%0, %1}, %2;" : "=f"(f.x), "=f"(f.y) : "l"(p));
    return f;
}

__global__ void __launch_bounds__(NTHREADS, 2)
rvq_kernel(const float* __restrict__ z,
           const float* __restrict__ cbooks,
           float* __restrict__ outZq,
           float* __restrict__ outIdx,
           float* __restrict__ outLogits)
{
    extern __shared__ float smem[];
    float* cb_s    = smem + OFF_CB;
    float* res_s   = smem + OFF_RES;
    float* rn_s    = smem + OFF_RN;
    float* cbn_s   = smem + OFF_CBN;
    float* bestv_s = smem + OFF_BESTV;
    int*   besti_s = (int*)(smem + OFF_BESTI);

    const int tid     = threadIdx.x;
    const int tokBase = blockIdx.x * TILE_T;

    // GEMM thread mapping: 8 token-groups x 16 code-groups
    const int ty = tid >> 4;        // 0..7
    const int tx = tid & 15;        // 0..15
    const int t0 = ty * 8;
    const int c0 = tx * 4;

    // ---- init: res = z chunk 0 (transposed into smem), rn = ||res||^2 ----
    {
        const int t = tid >> 1, h = tid & 1;
        const int tok = tokBase + t;
        const float4* z4p = (const float4*)(z + (size_t)tok * DD) + h * 8;
        float sq = 0.f;
        #pragma unroll
        for (int j = 0; j < 8; j++) {
            float4 zv = z4p[j];
            int d = h * 32 + j * 4;
            res_s[(d + 0) * RES_P + t] = zv.x;
            res_s[(d + 1) * RES_P + t] = zv.y;
            res_s[(d + 2) * RES_P + t] = zv.z;
            res_s[(d + 3) * RES_P + t] = zv.w;
            sq += zv.x * zv.x + zv.y * zv.y + zv.z * zv.z + zv.w * zv.w;
        }
        float o = __shfl_xor_sync(0xffffffffu, sq, 1);
        if (h == 0) rn_s[t] = sq + o;
    }

    for (int i = 0; i < NCB; i++) {
        if (tid < TILE_T) { bestv_s[tid] = 3.4e38f; besti_s[tid] = 0; }
        __syncthreads();   // res_s, rn_s, best init ready

        for (int kb = 0; kb < KCODES / TILE_K; kb++) {
            // ---- load cb block, transposed (register transpose, STS.128) ----
            const float4* cbG =
                (const float4*)(cbooks + ((size_t)i * KCODES + (size_t)kb * TILE_K) * CD);
            #pragma unroll
            for (int r = 0; r < 4; r++) {
                int u  = tid + r * NTHREADS;          // 0..511
                int k0 = (u & 31) * 4;                // code base
                int dg = u >> 5;                      // dim group 0..15
                float4 v0 = cbG[(k0 + 0) * 16 + dg];
                float4 v1 = cbG[(k0 + 1) * 16 + dg];
                float4 v2 = cbG[(k0 + 2) * 16 + dg];
                float4 v3 = cbG[(k0 + 3) * 16 + dg];
                int d0 = dg * 4;
                *(float4*)(cb_s + (d0 + 0) * CB_P + k0) = make_float4(v0.x, v1.x, v2.x, v3.x);
                *(float4*)(cb_s + (d0 + 1) * CB_P + k0) = make_float4(v0.y, v1.y, v2.y, v3.y);
                *(float4*)(cb_s + (d0 + 2) * CB_P + k0) = make_float4(v0.z, v1.z, v2.z, v3.z);
                *(float4*)(cb_s + (d0 + 3) * CB_P + k0) = make_float4(v0.w, v1.w, v2.w, v3.w);
            }
            __syncthreads();

            // ---- code norms (one code per thread) ----
            {
                float s = 0.f;
                #pragma unroll 16
                for (int d = 0; d < CD; d++) {
                    float v = cb_s[d * CB_P + tid];
                    s += v * v;
                }
                cbn_s[tid] = s;
            }

            // ---- GEMM: 8 tokens x 8 codes per thread, f32x2 packed FMA ----
            ull acc[8][4];
            #pragma unroll
            for (int a = 0; a < 8; a++)
                #pragma unroll
                for (int b = 0; b < 4; b++) acc[a][b] = 0ull;

            #pragma unroll 16
            for (int d = 0; d < CD; d++) {
                const float* rp = res_s + d * RES_P + t0;
                float4 ra = *(const float4*)rp;
                float4 rb = *(const float4*)(rp + 4);
                const float* cp = cb_s + d * CB_P + c0;
                ulonglong2 cA = *(const ulonglong2*)cp;          // codes c0,c0+1 | c0+2,c0+3
                ulonglong2 cB = *(const ulonglong2*)(cp + 64);   // codes +64
                float rv[8] = {ra.x, ra.y, ra.z, ra.w, rb.x, rb.y, rb.z, rb.w};
                #pragma unroll
                for (int tt = 0; tt < 8; tt++) {
                    ull r = dup_f32x2(rv[tt]);
                    fma_f32x2(acc[tt][0], r, cA.x);
                    fma_f32x2(acc[tt][1], r, cA.y);
                    fma_f32x2(acc[tt][2], r, cB.x);
                    fma_f32x2(acc[tt][3], r, cB.y);
                }
            }
            __syncthreads();   // cbn_s visible; GEMM smem reads done

            // ---- epilogue: logits store + per-token argmin ----
            {
                const float cn0 = cbn_s[c0 + 0], cn1 = cbn_s[c0 + 1];
                const float cn2 = cbn_s[c0 + 2], cn3 = cbn_s[c0 + 3];
                const float cn4 = cbn_s[c0 + 64], cn5 = cbn_s[c0 + 65];
                const float cn6 = cbn_s[c0 + 66], cn7 = cbn_s[c0 + 67];
                const int cg = kb * TILE_K + c0;

                #pragma unroll
                for (int tt = 0; tt < 8; tt++) {
                    const int t   = t0 + tt;
                    const int tok = tokBase + t;
                    const int b   = tok >> 11;
                    const int tl  = tok & (TSEQ - 1);
                    const float rn = rn_s[t];

                    float2 p0 = unpack_f32x2(acc[tt][0]);
                    float2 p1 = unpack_f32x2(acc[tt][1]);
                    float2 p2 = unpack_f32x2(acc[tt][2]);
                    float2 p3 = unpack_f32x2(acc[tt][3]);

                    float4 oA = make_float4(2.f * p0.x - rn - cn0, 2.f * p0.y - rn - cn1,
                                            2.f * p1.x - rn - cn2, 2.f * p1.y - rn - cn3);
                    float4 oB = make_float4(2.f * p2.x - rn - cn4, 2.f * p2.y - rn - cn5,
                                            2.f * p3.x - rn - cn6, 2.f * p3.y - rn - cn7);

                    size_t base = (((size_t)(b * NCB + i)) * TSEQ + tl) * KCODES;
                    *(float4*)(outLogits + base + cg)      = oA;
                    *(float4*)(outLogits + base + cg + 64) = oB;

                    // argmin key = cbn - 2*dot = -logit - rn  (rn cancels per token)
                    float mv = -oA.x - rn; int mi = cg;
                    float v;
                    v = -oA.y - rn; if (v < mv) { mv = v; mi = cg + 1; }
                    v = -oA.z - rn; if (v < mv) { mv = v; mi = cg + 2; }
                    v = -oA.w - rn; if (v < mv) { mv = v; mi = cg + 3; }
                    v = -oB.x - rn; if (v < mv) { mv = v; mi = cg + 64; }
                    v = -oB.y - rn; if (v < mv) { mv = v; mi = cg + 65; }
                    v = -oB.z - rn; if (v < mv) { mv = v; mi = cg + 66; }
                    v = -oB.w - rn; if (v < mv) { mv = v; mi = cg + 67; }

                    #pragma unroll
                    for (int off = 8; off > 0; off >>= 1) {
                        float ov = __shfl_xor_sync(0xffffffffu, mv, off);
                        int   oi = __shfl_xor_sync(0xffffffffu, mi, off);
                        if (ov < mv || (ov == mv && oi < mi)) { mv = ov; mi = oi; }
                    }
                    if (tx == 0) {
                        if (mv < bestv_s[t]) { bestv_s[t] = mv; besti_s[t] = mi; }
                    }
                }
            }
            __syncthreads();   // best final for this kb; cb_s/cbn_s reusable
        }

        // ---- finish stage: indices, z_q, residual update, new rn ----
        if (tid < TILE_T) {
            const int t = tid;
            const int tok = tokBase + t;
            const int b = tok >> 11, tl = tok & (TSEQ - 1);
            outIdx[((size_t)b * NCB + i) * TSEQ + tl] = (float)besti_s[t];
        }
        {
            const int t = tid >> 1, h = tid & 1;
            const int tok = tokBase + t;
            const int idx = besti_s[t];
            const float4* q4p =
                (const float4*)(cbooks + ((size_t)i * KCODES + idx) * CD) + h * 8;
            float4* zq4p = (float4*)(outZq + (size_t)tok * DD + i * CD) + h * 8;
            float sq = 0.f;
            if (i < NCB - 1) {
                const float4* z4p =
                    (const float4*)(z + (size_t)tok * DD + (i + 1) * CD) + h * 8;
                #pragma unroll
                for (int j = 0; j < 8; j++) {
                    float4 q = q4p[j];
                    zq4p[j] = q;
                    float4 zv = z4p[j];
                    int d = h * 32 + j * 4;
                    float r0 = zv.x + res_s[(d + 0) * RES_P + t] - q.x;
                    float r1 = zv.y + res_s[(d + 1) * RES_P + t] - q.y;
                    float r2 = zv.z + res_s[(d + 2) * RES_P + t] - q.z;
                    float r3 = zv.w + res_s[(d + 3) * RES_P + t] - q.w;
                    res_s[(d + 0) * RES_P + t] = r0;
                    res_s[(d + 1) * RES_P + t] = r1;
                    res_s[(d + 2) * RES_P + t] = r2;
                    res_s[(d + 3) * RES_P + t] = r3;
                    sq += r0 * r0 + r1 * r1 + r2 * r2 + r3 * r3;
                }
                float o = __shfl_xor_sync(0xffffffffu, sq, 1);
                if (h == 0) rn_s[t] = sq + o;
            } else {
                #pragma unroll
                for (int j = 0; j < 8; j++) zq4p[j] = q4p[j];
            }
        }
        // loop-top __syncthreads() guards res_s/rn_s for next stage
    }
}

extern "C" void kernel_launch(void* const* d_in, const int* in_sizes, int n_in,
                              void* d_out, int out_size) {
    const float* z      = (const float*)d_in[0];   // (8, 2048, 512) f32
    const float* cbooks = (const float*)d_in[1];   // (8, 1024, 64)  f32

    float* outZq     = (float*)d_out;                               // 8388608
    float* outIdx    = outZq + (size_t)NTOK * DD;                   // 131072
    float* outLogits = outIdx + (size_t)BB * NCB * TSEQ;            // 134217728

    cudaFuncSetAttribute(rvq_kernel, cudaFuncAttributeMaxDynamicSharedMemorySize,
                         SMEM_BYTES);
    rvq_kernel<<<NTOK / TILE_T, NTHREADS, SMEM_BYTES>>>(z, cbooks, outZq, outIdx,
                                                        outLogits);
}

// round 4
// speedup vs baseline: 1.5024x; 1.5016x over previous
#include <cuda_runtime.h>
#include <cstdint>

#define NCBK   8
#define KC     1024
#define CDIM   64
#define TSEQQ  2048
#define DDIM   512
#define NTOKN  16384
#define MT     128
#define THREADS 256
#define TOTCH  64          // 8 stages * 8 chunks of 128 codes

// smem byte offsets
#define SM_CBN   131072u                 // after 2*64KB B buffers
#define SM_STG   132096u                 // staging 128 x 132 floats
#define SM_TOTAL 199680
#define STG_P    132

// Codebook B fragments (m16n8k8 layout), hi block then lo block per chunk
__device__ __align__(128) float g_Bfrag[TOTCH * 16384];
__device__ __align__(128) float g_cbnC[TOTCH * 128];

__device__ __forceinline__ uint32_t f2tf(float v) {
    uint32_t r; asm("cvt.rna.tf32.f32 %0,%1;" : "=r"(r) : "f"(v)); return r;
}
__device__ __forceinline__ uint32_t smem_u32(const void* p) {
    uint32_t a;
    asm("{ .reg .u64 t; cvta.to.shared.u64 t,%1; cvt.u32.u64 %0,t; }" : "=r"(a) : "l"(p));
    return a;
}
__device__ __forceinline__ void cpa16(uint32_t d, const void* s) {
    asm volatile("cp.async.cg.shared.global [%0],[%1],16;" :: "r"(d), "l"(s));
}
__device__ __forceinline__ void cp_commit() { asm volatile("cp.async.commit_group;" ::: "memory"); }
__device__ __forceinline__ void cp_wait1()  { asm volatile("cp.async.wait_group 1;" ::: "memory"); }
__device__ __forceinline__ void cp_wait0()  { asm volatile("cp.async.wait_group 0;" ::: "memory"); }

__device__ __forceinline__ float2 lds64(uint32_t a) {
    float2 v;
    asm volatile("ld.shared.v2.f32 {%0,%1},[%2];" : "=f"(v.x), "=f"(v.y) : "r"(a));
    return v;
}
__device__ __forceinline__ float4 lds128(uint32_t a) {
    float4 v;
    asm volatile("ld.shared.v4.f32 {%0,%1,%2,%3},[%4];"
                 : "=f"(v.x), "=f"(v.y), "=f"(v.z), "=f"(v.w) : "r"(a));
    return v;
}
__device__ __forceinline__ void sts64(uint32_t a, float x, float y) {
    asm volatile("st.shared.v2.f32 [%0],{%1,%2};" :: "r"(a), "f"(x), "f"(y));
}

__device__ __forceinline__ void mma8(float c[4], const float a[4], float b0, float b1) {
    asm volatile(
        "mma.sync.aligned.m16n8k8.row.col.f32.tf32.tf32.f32 "
        "{%0,%1,%2,%3},{%4,%5,%6,%7},{%8,%9},{%0,%1,%2,%3};"
        : "+f"(c[0]), "+f"(c[1]), "+f"(c[2]), "+f"(c[3])
        : "r"(__float_as_uint(a[0])), "r"(__float_as_uint(a[1])),
          "r"(__float_as_uint(a[2])), "r"(__float_as_uint(a[3])),
          "r"(__float_as_uint(b0)), "r"(__float_as_uint(b1)));
}

// ---------------- prep: pack codebooks as hi/lo tf32 B fragments + norms ----
__global__ void prep(const float* __restrict__ cb) {
    const int chunk = blockIdx.x;
    const int i = chunk >> 3, kb = chunk & 7;
    const float* cbs = cb + (size_t)i * KC * CDIM;
    const int cbase = kb * 128;
    float* dsth = g_Bfrag + (size_t)chunk * 16384;
    float* dstl = dsth + 8192;
    for (int u = threadIdx.x; u < 4096; u += blockDim.x) {
        const int ks = u >> 9, nt = (u >> 5) & 15, t = u & 31;
        const int code = cbase + nt * 8 + (t >> 2);
        const int d = ks * 8 + (t & 3);
        const float v0 = cbs[code * CDIM + d];
        const float v1 = cbs[code * CDIM + d + 4];
        const uint32_t h0 = f2tf(v0), h1 = f2tf(v1);
        const float l0 = v0 - __uint_as_float(h0);
        const float l1 = v1 - __uint_as_float(h1);
        ((float2*)dsth)[u] = make_float2(__uint_as_float(h0), __uint_as_float(h1));
        ((float2*)dstl)[u] = make_float2(__uint_as_float(f2tf(l0)), __uint_as_float(f2tf(l1)));
    }
    if (threadIdx.x < 128) {
        const int code = cbase + threadIdx.x;
        float s = 0.f;
        #pragma unroll
        for (int d = 0; d < CDIM; d++) { const float v = cbs[code * CDIM + d]; s += v * v; }
        g_cbnC[chunk * 128 + threadIdx.x] = s;
    }
}

// ---------------- main ----------------
__global__ void __launch_bounds__(THREADS, 1)
rvq_main(const float* __restrict__ z, const float* __restrict__ cbooks,
         float* __restrict__ outZq, float* __restrict__ outIdx,
         float* __restrict__ outLogits)
{
    extern __shared__ __align__(16) char sm[];
    const uint32_t smb = smem_u32(sm);

    const int tid = threadIdx.x;
    const int w = tid >> 5, t = tid & 31;
    const int q = t & 3, g = t >> 2;

    const int tokBase = blockIdx.x * MT;
    const int rowA = w * 16 + g;             // CTA row of fragment-row 0
    const int rowB = rowA + 8;
    const int tokA = tokBase + rowA, tokB = tokBase + rowB;
    const int bA = tokA >> 11, tlA = tokA & (TSEQQ - 1);
    const int bB = tokB >> 11, tlB = tokB & (TSEQQ - 1);

    const float* zA = z + (size_t)tokA * DDIM;
    const float* zB = z + (size_t)tokB * DDIM;

    // A fragments: residual hi/lo tf32 split (hi+lo reconstructs res to 2^-22)
    float ahi[8][4], alo[8][4];
    float rn0 = 0.f, rn1 = 0.f;
    #pragma unroll
    for (int m = 0; m < 16; m++) {
        const int d = 4 * m + q, ks = m >> 1, p = (m & 1) * 2;
        const float vA = zA[d], vB = zB[d];
        rn0 += vA * vA; rn1 += vB * vB;
        uint32_t h = f2tf(vA);
        ahi[ks][p] = __uint_as_float(h);
        alo[ks][p] = __uint_as_float(f2tf(vA - __uint_as_float(h)));
        h = f2tf(vB);
        ahi[ks][p + 1] = __uint_as_float(h);
        alo[ks][p + 1] = __uint_as_float(f2tf(vB - __uint_as_float(h)));
    }
    rn0 += __shfl_xor_sync(0xffffffffu, rn0, 1); rn0 += __shfl_xor_sync(0xffffffffu, rn0, 2);
    rn1 += __shfl_xor_sync(0xffffffffu, rn1, 1); rn1 += __shfl_xor_sync(0xffffffffu, rn1, 2);

    // prologue prefetch chunk 0
    {
        const char* src = (const char*)g_Bfrag;
        #pragma unroll
        for (int j = 0; j < 16; j++)
            cpa16(smb + (uint32_t)(tid + j * 256) * 16u, src + (size_t)(tid + j * 256) * 16);
        if (tid < 32) cpa16(smb + SM_CBN + (uint32_t)tid * 16u, (const char*)g_cbnC + tid * 16);
        cp_commit();
    }

    int c = 0;
    for (int i = 0; i < NCBK; i++) {
        float bv0 = 3.4e38f, bv1 = 3.4e38f;
        int bk0 = 0, bk1 = 0;

        for (int kb = 0; kb < 8; kb++) {
            const int buf = c & 1;
            if (c + 1 < TOTCH) {
                const int nb = (c + 1) & 1;
                const char* src = (const char*)(g_Bfrag + (size_t)(c + 1) * 16384);
                #pragma unroll
                for (int j = 0; j < 16; j++)
                    cpa16(smb + (uint32_t)nb * 65536u + (uint32_t)(tid + j * 256) * 16u,
                          src + (size_t)(tid + j * 256) * 16);
                if (tid < 32)
                    cpa16(smb + SM_CBN + (uint32_t)nb * 512u + (uint32_t)tid * 16u,
                          (const char*)(g_cbnC + (c + 1) * 128) + tid * 16);
                cp_commit();
                cp_wait1();
            } else {
                cp_wait0();
            }
            __syncthreads();   // B[buf] ready; staging free

            // ---- MMA: 16 n-tiles x 8 k-steps x 3 passes ----
            float acc[16][4];
            #pragma unroll
            for (int nt = 0; nt < 16; nt++)
                #pragma unroll
                for (int v = 0; v < 4; v++) acc[nt][v] = 0.f;

            const uint32_t bbase = smb + (uint32_t)buf * 65536u + (uint32_t)t * 8u;
            #pragma unroll
            for (int ks = 0; ks < 8; ks++) {
                const uint32_t kbase = bbase + (uint32_t)(ks * 512) * 8u;
                #pragma unroll
                for (int nt = 0; nt < 16; nt++) {
                    const uint32_t ha = kbase + (uint32_t)(nt * 32) * 8u;
                    const float2 bh = lds64(ha);
                    const float2 bl = lds64(ha + 32768u);
                    mma8(acc[nt], ahi[ks], bh.x, bh.y);
                    mma8(acc[nt], alo[ks], bh.x, bh.y);
                    mma8(acc[nt], ahi[ks], bl.x, bl.y);
                }
            }

            // ---- epilogue: logits + per-thread top-1, stage to smem ----
            const uint32_t cbb = smb + SM_CBN + (uint32_t)buf * 512u;
            const uint32_t stg = smb + SM_STG;
            #pragma unroll
            for (int nt = 0; nt < 16; nt++) {
                const float2 cn = lds64(cbb + (uint32_t)(nt * 8 + 2 * q) * 4u);
                const float kA0 = cn.x - 2.f * acc[nt][0];
                const float kA1 = cn.y - 2.f * acc[nt][1];
                const float kB0 = cn.x - 2.f * acc[nt][2];
                const float kB1 = cn.y - 2.f * acc[nt][3];
                const int kidx = kb * 128 + nt * 8 + 2 * q;
                if (kA0 < bv0) { bv0 = kA0; bk0 = kidx; }
                if (kA1 < bv0) { bv0 = kA1; bk0 = kidx + 1; }
                if (kB0 < bv1) { bv1 = kB0; bk1 = kidx; }
                if (kB1 < bv1) { bv1 = kB1; bk1 = kidx + 1; }
                sts64(stg + (uint32_t)(rowA * STG_P + nt * 8 + 2 * q) * 4u,
                      -kA0 - rn0, -kA1 - rn0);
                sts64(stg + (uint32_t)(rowB * STG_P + nt * 8 + 2 * q) * 4u,
                      -kB0 - rn1, -kB1 - rn1);
            }
            __syncthreads();   // staging complete

            // ---- coalesced flush: 128 rows x 128 cols ----
            #pragma unroll
            for (int it = 0; it < 16; it++) {
                const int rr = it * 8 + w;
                const float4 v = lds128(stg + (uint32_t)(rr * STG_P + t * 4) * 4u);
                const int tok = tokBase + rr;
                const int bb = tok >> 11, tl = tok & (TSEQQ - 1);
                float* dst = outLogits + ((size_t)(bb * NCBK + i) * TSEQQ + tl) * KC
                             + kb * 128 + t * 4;
                *(float4*)dst = v;
            }
            c++;
        }

        // ---- stage end: quad argmin merge (first-min ties) ----
        #pragma unroll
        for (int x = 1; x <= 2; x <<= 1) {
            float ov = __shfl_xor_sync(0xffffffffu, bv0, x);
            int   oi = __shfl_xor_sync(0xffffffffu, bk0, x);
            if (ov < bv0 || (ov == bv0 && oi < bk0)) { bv0 = ov; bk0 = oi; }
            ov = __shfl_xor_sync(0xffffffffu, bv1, x);
            oi = __shfl_xor_sync(0xffffffffu, bk1, x);
            if (ov < bv1 || (ov == bv1 && oi < bk1)) { bv1 = ov; bk1 = oi; }
        }
        if (q == 0) {
            outIdx[(size_t)(bA * NCBK + i) * TSEQQ + tlA] = (float)bk0;
            outIdx[(size_t)(bB * NCBK + i) * TSEQQ + tlB] = (float)bk1;
        }

        // ---- gather q, write z_q, residual update + re-split ----
        const float* qp0 = cbooks + ((size_t)i * KC + bk0) * CDIM;
        const float* qp1 = cbooks + ((size_t)i * KC + bk1) * CDIM;
        float* zqA = outZq + (size_t)tokA * DDIM + i * CDIM;
        float* zqB = outZq + (size_t)tokB * DDIM + i * CDIM;
        float nr0 = 0.f, nr1 = 0.f;
        #pragma unroll
        for (int m = 0; m < 16; m++) {
            const int d = 4 * m + q, ks = m >> 1, p = (m & 1) * 2;
            const float q0 = __ldg(qp0 + d), q1 = __ldg(qp1 + d);
            zqA[d] = q0; zqB[d] = q1;
            if (i < NCBK - 1) {
                const float vA = zA[(i + 1) * CDIM + d] + (ahi[ks][p] + alo[ks][p]) - q0;
                const float vB = zB[(i + 1) * CDIM + d] + (ahi[ks][p + 1] + alo[ks][p + 1]) - q1;
                nr0 += vA * vA; nr1 += vB * vB;
                uint32_t h = f2tf(vA);
                ahi[ks][p] = __uint_as_float(h);
                alo[ks][p] = __uint_as_float(f2tf(vA - __uint_as_float(h)));
                h = f2tf(vB);
                ahi[ks][p + 1] = __uint_as_float(h);
                alo[ks][p + 1] = __uint_as_float(f2tf(vB - __uint_as_float(h)));
            }
        }
        if (i < NCBK - 1) {
            nr0 += __shfl_xor_sync(0xffffffffu, nr0, 1);
            nr0 += __shfl_xor_sync(0xffffffffu, nr0, 2);
            nr1 += __shfl_xor_sync(0xffffffffu, nr1, 1);
            nr1 += __shfl_xor_sync(0xffffffffu, nr1, 2);
            rn0 = nr0; rn1 = nr1;
        }
    }
}

extern "C" void kernel_launch(void* const* d_in, const int* in_sizes, int n_in,
                              void* d_out, int out_size) {
    const float* z      = (const float*)d_in[0];   // (8, 2048, 512) f32
    const float* cbooks = (const float*)d_in[1];   // (8, 1024, 64)  f32

    float* outZq     = (float*)d_out;
    float* outIdx    = outZq + (size_t)NTOKN * DDIM;
    float* outLogits = outIdx + (size_t)NCBK * NTOKN;

    cudaFuncSetAttribute(rvq_main, cudaFuncAttributeMaxDynamicSharedMemorySize, SM_TOTAL);

    prep<<<TOTCH, 256>>>(cbooks);
    rvq_main<<<NTOKN / MT, THREADS, SM_TOTAL>>>(z, cbooks, outZq, outIdx, outLogits);
}